// round 2
// baseline (speedup 1.0000x reference)
#include <cuda_runtime.h>

#define L_SEQ 512
#define T_TAGS 64
#define WARPS 4
#define BPW 2   // lane-parallel batches per warp (16 lanes each)

#define FMA2(d, a, b) asm("fma.rn.f32x2 %0, %1, %2, %0;" : "+l"(d) : "l"(a), "l"(b))

__global__ __launch_bounds__(128, 1)
void crf_kernel(const float* __restrict__ logits,
                const unsigned int* __restrict__ tagw,
                const int* __restrict__ mask,
                const float* __restrict__ trans,
                float* __restrict__ out)
{
    __shared__ float expT_s[64 * 64];
    // dup-pair p buffer, double-buffered: [buf][warp][b_sub][128 floats (64 pairs)] + pad
    __shared__ float pbuf[2][WARPS][BPW][136];

    const int tid = threadIdx.x;
    const int w = tid >> 5, lane = tid & 31;
    const int b_sub = lane >> 4;          // which lane-parallel batch
    const int jl = lane & 15;             // j-lane within 16-lane group
    const int j0 = jl << 2;               // 4 consecutive tags per lane
    const int b = (blockIdx.x * WARPS + w) * BPW + b_sub;

    // ---- build exp(trans) in smem ----
    for (int i = tid; i < 4096; i += 128)
        expT_s[i] = __expf(trans[i]);

    // ---- tag dtype detection (int64 little-endian => odd 32-bit words all 0) ----
    unsigned oddacc = 0;
    #pragma unroll
    for (int k = 0; k < 4; ++k) oddacc |= tagw[2 * (lane + 32 * k) + 1];
    const int is64 = __all_sync(0xffffffffu, oddacc == 0) ? 1 : 0;

    __syncthreads();

    // ---- register cache of expT rows 0..31, columns j0..j0+3 ----
    ulonglong2 ec[32];
    #pragma unroll
    for (int i = 0; i < 32; ++i)
        ec[i] = *(const ulonglong2*)&expT_s[i * 64 + j0];

    const float* lg = logits + (size_t)b * (L_SEQ * T_TAGS);
    const int mbase = b * L_SEQ;

    // ---- l = 0 ----
    float4 a0 = *(const float4*)(lg + j0);
    float al0 = a0.x, al1 = a0.y, al2 = a0.z, al3 = a0.w;

    int t0 = (int)tagw[is64 ? (mbase << 1) : mbase];
    float gold = 0.f;
    {
        float m0 = (float)mask[mbase];
        if (jl == (t0 >> 2)) {
            int c = t0 & 3;
            float ev = a0.x;
            ev = (c == 1) ? a0.y : ev;
            ev = (c == 2) ? a0.z : ev;
            ev = (c == 3) ? a0.w : ev;
            gold = ev * m0;
        }
    }
    int tprev = t0;

    // current-step operands (l = 1), prefetched
    float4 cem = *(const float4*)(lg + T_TAGS + j0);
    int cm = mask[mbase + 1];
    int ct = (int)tagw[is64 ? ((mbase + 1) << 1) : (mbase + 1)];

    for (int l = 1; l < L_SEQ; ++l) {
        const int buf = l & 1;

        // depth-1 software prefetch (clamped, branch-free)
        int lp = (l + 1 < L_SEQ) ? (l + 1) : (L_SEQ - 1);
        float4 nem = *(const float4*)(lg + lp * T_TAGS + j0);
        int nm = mask[mbase + lp];
        int nt = (int)tagw[is64 ? ((mbase + lp) << 1) : (mbase + lp)];

        // ---- group-uniform shift: alpha[j=0] (single shuffle, width 16) ----
        float shift = __shfl_sync(0xffffffffu, al0, 0, 16);

        // ---- p = exp(alpha - shift), store as duplicated pairs ----
        float p0 = __expf(al0 - shift);
        float p1 = __expf(al1 - shift);
        float p2 = __expf(al2 - shift);
        float p3 = __expf(al3 - shift);
        float* pb = &pbuf[buf][w][b_sub][0];
        *(float4*)(pb + 8 * jl)     = make_float4(p0, p0, p1, p1);
        *(float4*)(pb + 8 * jl + 4) = make_float4(p2, p2, p3, p3);
        __syncwarp();

        // ---- s[j] = sum_i p[i] * expT[i][j] ----
        unsigned long long s01 = 0ull, s23 = 0ull;

        // rows 0..31: expT from registers
        #pragma unroll
        for (int i2 = 0; i2 < 16; ++i2) {
            ulonglong2 pp = *(const ulonglong2*)(pb + 4 * i2);   // pairs for i=2*i2, 2*i2+1
            FMA2(s01, pp.x, ec[2 * i2].x);
            FMA2(s23, pp.x, ec[2 * i2].y);
            FMA2(s01, pp.y, ec[2 * i2 + 1].x);
            FMA2(s23, pp.y, ec[2 * i2 + 1].y);
        }
        // rows 32..63: expT from smem
        #pragma unroll
        for (int i2 = 16; i2 < 32; ++i2) {
            ulonglong2 pp = *(const ulonglong2*)(pb + 4 * i2);
            ulonglong2 e0 = *(const ulonglong2*)&expT_s[(2 * i2) * 64 + j0];
            ulonglong2 e1 = *(const ulonglong2*)&expT_s[(2 * i2 + 1) * 64 + j0];
            FMA2(s01, pp.x, e0.x);
            FMA2(s23, pp.x, e0.y);
            FMA2(s01, pp.y, e1.x);
            FMA2(s23, pp.y, e1.y);
        }

        float s0, s1, s2, s3;
        asm("mov.b64 {%0, %1}, %2;" : "=f"(s0), "=f"(s1) : "l"(s01));
        asm("mov.b64 {%0, %1}, %2;" : "=f"(s2), "=f"(s3) : "l"(s23));

        float n0 = shift + __logf(s0) + cem.x;
        float n1 = shift + __logf(s1) + cem.y;
        float n2 = shift + __logf(s2) + cem.z;
        float n3 = shift + __logf(s3) + cem.w;

        bool keep = cm > 0;
        al0 = keep ? n0 : al0;
        al1 = keep ? n1 : al1;
        al2 = keep ? n2 : al2;
        al3 = keep ? n3 : al3;

        // ---- gold score accumulation (off critical path) ----
        float lm = (float)cm;
        if (jl == (ct >> 2)) {
            int c = ct & 3;
            float ev = cem.x;
            ev = (c == 1) ? cem.y : ev;
            ev = (c == 2) ? cem.z : ev;
            ev = (c == 3) ? cem.w : ev;
            gold += ev * lm;
        }
        if (jl == 0) gold += __ldg(&trans[tprev * 64 + ct]) * lm;
        tprev = ct;

        cem = nem; cm = nm; ct = nt;
    }

    // ---- final logsumexp over alpha (exact max here, once) ----
    float mx = fmaxf(fmaxf(al0, al1), fmaxf(al2, al3));
    mx = fmaxf(mx, __shfl_xor_sync(0xffffffffu, mx, 1));
    mx = fmaxf(mx, __shfl_xor_sync(0xffffffffu, mx, 2));
    mx = fmaxf(mx, __shfl_xor_sync(0xffffffffu, mx, 4));
    mx = fmaxf(mx, __shfl_xor_sync(0xffffffffu, mx, 8));

    float s = __expf(al0 - mx) + __expf(al1 - mx) + __expf(al2 - mx) + __expf(al3 - mx);
    s += __shfl_xor_sync(0xffffffffu, s, 1);
    s += __shfl_xor_sync(0xffffffffu, s, 2);
    s += __shfl_xor_sync(0xffffffffu, s, 4);
    s += __shfl_xor_sync(0xffffffffu, s, 8);

    gold += __shfl_xor_sync(0xffffffffu, gold, 1);
    gold += __shfl_xor_sync(0xffffffffu, gold, 2);
    gold += __shfl_xor_sync(0xffffffffu, gold, 4);
    gold += __shfl_xor_sync(0xffffffffu, gold, 8);

    if (jl == 0) out[b] = (mx + __logf(s)) - gold;
}

extern "C" void kernel_launch(void* const* d_in, const int* in_sizes, int n_in,
                              void* d_out, int out_size)
{
    const float*        logits = (const float*)d_in[0];
    const unsigned int* tagw   = (const unsigned int*)d_in[1];
    const int*          mask   = (const int*)d_in[2];
    const float*        trans  = (const float*)d_in[3];
    float*              out    = (float*)d_out;

    crf_kernel<<<128, 128>>>(logits, tagw, mask, trans, out);
}

// round 3
// speedup vs baseline: 1.6430x; 1.6430x over previous
#include <cuda_runtime.h>

#define L_SEQ 512
#define T_TAGS 64
#define WARPS 8     // 1 chain per warp, 8 chains per CTA

#define FMA2(d, a, b) asm("fma.rn.f32x2 %0, %1, %2, %0;" : "+l"(d) : "l"(a), "l"(b))
#define ADD2(d, a)    asm("add.rn.f32x2 %0, %0, %1;"      : "+l"(d) : "l"(a))

__device__ __forceinline__ unsigned long long pack2(float x, float y) {
    unsigned long long r;
    asm("mov.b64 %0, {%1, %2};" : "=l"(r) : "f"(x), "f"(y));
    return r;
}

__global__ __launch_bounds__(256, 1)
void crf_kernel(const float* __restrict__ logits,
                const unsigned int* __restrict__ tagw,
                const int* __restrict__ mask,
                const float* __restrict__ trans,
                float* __restrict__ out)
{
    // dup-pair p buffer, double-buffered per warp: 128 floats + pad
    __shared__ float pbuf[2][WARPS][132];

    const int tid  = threadIdx.x;
    const int w    = tid >> 5;
    const int lane = tid & 31;
    const int j0   = lane << 1;                 // this lane owns tags j0, j0+1
    const int b    = blockIdx.x * WARPS + w;    // one chain per warp

    // ---- tag dtype detection (int64 LE => odd 32-bit words all zero) ----
    unsigned oddacc = 0;
    #pragma unroll
    for (int k = 0; k < 4; ++k) oddacc |= tagw[2 * (lane + 32 * k) + 1];
    const int is64 = __all_sync(0xffffffffu, oddacc == 0) ? 1 : 0;

    // ---- full register cache of exp(trans): rows 0..63, cols j0..j0+1 ----
    unsigned long long ec[64];
    #pragma unroll
    for (int i = 0; i < 64; ++i) {
        float2 t = *(const float2*)&trans[i * 64 + j0];
        ec[i] = pack2(__expf(t.x), __expf(t.y));
    }

    const float* lg = logits + (size_t)b * (L_SEQ * T_TAGS);
    const int mbase = b * L_SEQ;

    // ---- l = 0 ----
    float2 a0 = *(const float2*)(lg + j0);
    float al0 = a0.x, al1 = a0.y;

    int t0 = (int)tagw[is64 ? (mbase << 1) : mbase];
    float gold = 0.f;
    {
        float m0 = (float)mask[mbase];
        if ((t0 >> 1) == lane) gold = ((t0 & 1) ? a0.y : a0.x) * m0;
    }
    int tprev = t0;

    // current-step (l = 1) operands, prefetched
    float2 cem = *(const float2*)(lg + T_TAGS + j0);
    int cm = mask[mbase + 1];
    int ct = (int)tagw[is64 ? ((mbase + 1) << 1) : (mbase + 1)];

    for (int l = 1; l < L_SEQ; ++l) {
        const int buf = l & 1;

        // depth-1 prefetch (clamped) + gold transition load, all issued early
        const int lp = (l + 1 < L_SEQ) ? (l + 1) : (L_SEQ - 1);
        float2 nem = *(const float2*)(lg + lp * T_TAGS + j0);
        int nm = mask[mbase + lp];
        int nt = (int)tagw[is64 ? ((mbase + lp) << 1) : (mbase + lp)];
        float tv = __ldg(&trans[tprev * 64 + ct]);

        // ---- group-uniform shift: alpha[0] (one shuffle) ----
        float shift = __shfl_sync(0xffffffffu, al0, 0);

        // ---- p = exp(alpha - shift), stored as duplicated pairs ----
        float p0 = __expf(al0 - shift);
        float p1 = __expf(al1 - shift);
        float* pb = &pbuf[buf][w][0];
        *(float4*)(pb + 4 * lane) = make_float4(p0, p0, p1, p1);
        __syncwarp();

        // ---- s[j] = sum_i p[i] * expT[i][j], expT entirely in registers ----
        unsigned long long sA = 0ull, sB = 0ull, sC = 0ull, sD = 0ull;
        #pragma unroll
        for (int k = 0; k < 32; ++k) {
            ulonglong2 pp = *(const ulonglong2*)(pb + 4 * k);  // broadcast: pairs i=2k, 2k+1
            if (k & 1) {
                FMA2(sC, pp.x, ec[2 * k]);
                FMA2(sD, pp.y, ec[2 * k + 1]);
            } else {
                FMA2(sA, pp.x, ec[2 * k]);
                FMA2(sB, pp.y, ec[2 * k + 1]);
            }
        }
        ADD2(sA, sB);
        ADD2(sC, sD);
        ADD2(sA, sC);

        float s0, s1;
        asm("mov.b64 {%0, %1}, %2;" : "=f"(s0), "=f"(s1) : "l"(sA));

        float n0 = shift + __logf(s0) + cem.x;
        float n1 = shift + __logf(s1) + cem.y;

        bool keep = cm > 0;
        al0 = keep ? n0 : al0;
        al1 = keep ? n1 : al1;

        // ---- gold score ----
        float lm = (float)cm;
        if ((ct >> 1) == lane) gold += ((ct & 1) ? cem.y : cem.x) * lm;
        if (lane == 0) gold += tv * lm;
        tprev = ct;

        cem = nem; cm = nm; ct = nt;
    }

    // ---- final logsumexp over the 64 alphas (2 per lane) ----
    float mx = fmaxf(al0, al1);
    #pragma unroll
    for (int d = 1; d < 32; d <<= 1)
        mx = fmaxf(mx, __shfl_xor_sync(0xffffffffu, mx, d));

    float s = __expf(al0 - mx) + __expf(al1 - mx);
    #pragma unroll
    for (int d = 1; d < 32; d <<= 1)
        s += __shfl_xor_sync(0xffffffffu, s, d);

    #pragma unroll
    for (int d = 1; d < 32; d <<= 1)
        gold += __shfl_xor_sync(0xffffffffu, gold, d);

    if (lane == 0) out[b] = (mx + __logf(s)) - gold;
}

extern "C" void kernel_launch(void* const* d_in, const int* in_sizes, int n_in,
                              void* d_out, int out_size)
{
    const float*        logits = (const float*)d_in[0];
    const unsigned int* tagw   = (const unsigned int*)d_in[1];
    const int*          mask   = (const int*)d_in[2];
    const float*        trans  = (const float*)d_in[3];
    float*              out    = (float*)d_out;

    crf_kernel<<<128, 256>>>(logits, tagw, mask, trans, out);
}